// round 1
// baseline (speedup 1.0000x reference)
#include <cuda_runtime.h>
#include <math.h>

#define HW   4096
#define CH   256
#define CRr  128
#define NB   4
#define BQ   64
#define BK   64

// Scratch for q/k/v activations: [N][512][HW] (q rows 0..127, k 128..255, v 256..511)
__device__ float g_qkv[(size_t)NB * 512 * HW];

// ---------------------------------------------------------------------------
// Stage 1: stacked 1x1 conv GEMM  out[o][hw] = PReLU( sum_c W[o][c]*x[c][hw] + b[o] )
// W rows: 0..127 -> w1, 128..255 -> w2, 256..511 -> wa
// ---------------------------------------------------------------------------
__global__ void __launch_bounds__(256) stage1_kernel(
    const float* __restrict__ x,
    const float* __restrict__ w1, const float* __restrict__ b1, const float* __restrict__ a1,
    const float* __restrict__ w2, const float* __restrict__ b2, const float* __restrict__ a2,
    const float* __restrict__ wa, const float* __restrict__ ba, const float* __restrict__ aa)
{
    __shared__ float As[32][68];   // [kc][oo], padded stride 68
    __shared__ float Bs[32][64];   // [kc][hh]

    const int hbase = blockIdx.x * 64;
    const int obase = blockIdx.y * 64;
    const int n     = blockIdx.z;
    const int tid   = threadIdx.x;
    const int ty = tid >> 4, tx = tid & 15;

    const float* xb = x + (size_t)n * CH * HW;
    float acc[4][4] = {};

    for (int ct = 0; ct < CH; ct += 32) {
        __syncthreads();
        // Load A tile (weights, transposed into [kc][oo])
        for (int idx = tid; idx < 64 * 32; idx += 256) {
            int oo = idx >> 5, kc = idx & 31;
            int o = obase + oo;
            const float* wp;
            if (o < 128)      wp = w1 + (size_t)o * CH;
            else if (o < 256) wp = w2 + (size_t)(o - 128) * CH;
            else              wp = wa + (size_t)(o - 256) * CH;
            As[kc][oo] = wp[ct + kc];
        }
        // Load B tile (x)
        for (int idx = tid; idx < 32 * 64; idx += 256) {
            int kc = idx >> 6, hh = idx & 63;
            Bs[kc][hh] = xb[(size_t)(ct + kc) * HW + hbase + hh];
        }
        __syncthreads();
        #pragma unroll
        for (int kc = 0; kc < 32; ++kc) {
            float4 a4 = *(const float4*)&As[kc][4 * ty];
            float4 b4 = *(const float4*)&Bs[kc][4 * tx];
            float av[4] = {a4.x, a4.y, a4.z, a4.w};
            float bv[4] = {b4.x, b4.y, b4.z, b4.w};
            #pragma unroll
            for (int r = 0; r < 4; ++r)
                #pragma unroll
                for (int s = 0; s < 4; ++s)
                    acc[r][s] += av[r] * bv[s];
        }
    }

    // Epilogue: bias + PReLU, write to scratch
    #pragma unroll
    for (int r = 0; r < 4; ++r) {
        int o = obase + 4 * ty + r;
        float bias, slope;
        if (o < 128)      { bias = b1[o];       slope = a1[0]; }
        else if (o < 256) { bias = b2[o - 128]; slope = a2[0]; }
        else              { bias = ba[o - 256]; slope = aa[0]; }
        #pragma unroll
        for (int s = 0; s < 4; ++s) {
            float v = acc[r][s] + bias;
            v = (v >= 0.f) ? v : slope * v;
            g_qkv[((size_t)n * 512 + o) * HW + hbase + 4 * tx + s] = v;
        }
    }
}

// ---------------------------------------------------------------------------
// Flash attention: per CTA = (batch, 64-query tile). Online softmax over keys.
//   S[i][j] = sum_c Q[c][qi]*K[c][kj]  (c = 0..127)
//   O[q][c] += P[q][k]*V[c][k],  final: O/l + x  (written as [c][hw])
// ---------------------------------------------------------------------------
#define OFF_Q 0
#define OFF_K 8192
#define OFF_P 16384            /* [64][65] */
#define OFF_V 20544            /* [64][257] transposed: Vs[k][c] */
#define OFF_M 36992
#define OFF_L 37056
#define OFF_CF 37120
#define SMEM_FLOATS 37184
#define SMEM_BYTES (SMEM_FLOATS * 4)

__global__ void __launch_bounds__(256) flash_kernel(
    const float* __restrict__ x, float* __restrict__ out)
{
    extern __shared__ float sm[];
    float* Qs   = sm + OFF_Q;    // [128][64]
    float* Ks   = sm + OFF_K;    // [128][64]
    float* Ps   = sm + OFF_P;    // [64][65]
    float* Vs   = sm + OFF_V;    // [64][257]
    float* mrow = sm + OFF_M;
    float* lrow = sm + OFF_L;
    float* crow = sm + OFF_CF;

    const int qt = blockIdx.x, n = blockIdx.y;
    const int qbase = qt * BQ;
    const int tid = threadIdx.x;

    const float* Q = g_qkv + (size_t)n * 512 * HW;
    const float* K = Q + (size_t)CRr * HW;
    const float* V = Q + (size_t)2 * CRr * HW;

    // Load Q tile [c][i]
    for (int idx = tid; idx < CRr * BQ; idx += 256) {
        int c = idx >> 6, i = idx & 63;
        Qs[c * BQ + i] = Q[(size_t)c * HW + qbase + i];
    }
    if (tid < BQ) { mrow[tid] = -INFINITY; lrow[tid] = 0.f; }

    // Phase A thread ids (16x16, 4x4 microtile)
    const int ty = tid >> 4, tx = tid & 15;
    // Phase B thread ids (8x32, 8q x 8c microtile, c interleaved stride 32)
    const int tq = tid >> 5, tc = tid & 31;

    float acc[8][8] = {};

    for (int kt = 0; kt < HW / BK; ++kt) {
        const int kbase = kt * BK;
        __syncthreads();
        // Load K tile [c][j]
        for (int idx = tid; idx < CRr * BK; idx += 256) {
            int c = idx >> 6, j = idx & 63;
            Ks[c * BK + j] = K[(size_t)c * HW + kbase + j];
        }
        // Load V tile transposed: Vs[k][c]
        for (int idx = tid; idx < CH * BK; idx += 256) {
            int c = idx >> 6, k = idx & 63;
            Vs[k * 257 + c] = V[(size_t)c * HW + kbase + k];
        }
        __syncthreads();

        // Phase A: S = Q^T K  (inner dim 128)
        float s[4][4] = {};
        #pragma unroll 4
        for (int c = 0; c < CRr; ++c) {
            float4 a4 = *(const float4*)&Qs[c * BQ + 4 * ty];
            float4 b4 = *(const float4*)&Ks[c * BK + 4 * tx];
            float av[4] = {a4.x, a4.y, a4.z, a4.w};
            float bv[4] = {b4.x, b4.y, b4.z, b4.w};
            #pragma unroll
            for (int r = 0; r < 4; ++r)
                #pragma unroll
                for (int ss = 0; ss < 4; ++ss)
                    s[r][ss] += av[r] * bv[ss];
        }
        #pragma unroll
        for (int r = 0; r < 4; ++r)
            #pragma unroll
            for (int ss = 0; ss < 4; ++ss)
                Ps[(4 * ty + r) * 65 + 4 * tx + ss] = s[r][ss];
        __syncthreads();

        // Online softmax per row (64 rows, one thread each)
        if (tid < BQ) {
            const int r = tid;
            float mo = mrow[r];
            float mx = mo;
            #pragma unroll 8
            for (int j = 0; j < BK; ++j) mx = fmaxf(mx, Ps[r * 65 + j]);
            float cf = expf(mo - mx);           // exact 0 when mo == -inf
            float sum = 0.f;
            #pragma unroll 8
            for (int j = 0; j < BK; ++j) {
                float p = __expf(Ps[r * 65 + j] - mx);
                Ps[r * 65 + j] = p;
                sum += p;
            }
            mrow[r] = mx;
            lrow[r] = lrow[r] * cf + sum;
            crow[r] = cf;
        }
        __syncthreads();

        // Phase B: rescale + accumulate O += P * V^T
        #pragma unroll
        for (int qr = 0; qr < 8; ++qr) {
            float cf = crow[8 * tq + qr];
            #pragma unroll
            for (int cc = 0; cc < 8; ++cc) acc[qr][cc] *= cf;
        }
        #pragma unroll 2
        for (int k = 0; k < BK; ++k) {
            float p[8];
            #pragma unroll
            for (int qr = 0; qr < 8; ++qr) p[qr] = Ps[(8 * tq + qr) * 65 + k];
            #pragma unroll
            for (int cc = 0; cc < 8; ++cc) {
                float v = Vs[k * 257 + tc + 32 * cc];
                #pragma unroll
                for (int qr = 0; qr < 8; ++qr) acc[qr][cc] += p[qr] * v;
            }
        }
    }

    // Epilogue: divide by l, transpose through smem, add residual, write [c][hw]
    __syncthreads();
    float* Ts = sm;   // reuse Qs/Ks/Ps region as [256][65] (16640 floats < 20544)
    #pragma unroll
    for (int qr = 0; qr < 8; ++qr) {
        float inv = 1.f / lrow[8 * tq + qr];
        #pragma unroll
        for (int cc = 0; cc < 8; ++cc)
            Ts[(tc + 32 * cc) * 65 + 8 * tq + qr] = acc[qr][cc] * inv;
    }
    __syncthreads();
    const float* xb = x + (size_t)n * CH * HW;
    float* ob = out + (size_t)n * CH * HW;
    for (int idx = tid; idx < CH * BQ; idx += 256) {
        int c = idx >> 6, q = idx & 63;
        size_t g = (size_t)c * HW + qbase + q;
        ob[g] = Ts[c * 65 + q] + xb[g];
    }
}

// ---------------------------------------------------------------------------
extern "C" void kernel_launch(void* const* d_in, const int* in_sizes, int n_in,
                              void* d_out, int out_size)
{
    const float* x  = (const float*)d_in[0];
    const float* w1 = (const float*)d_in[1];
    const float* b1 = (const float*)d_in[2];
    const float* a1 = (const float*)d_in[3];
    const float* w2 = (const float*)d_in[4];
    const float* b2 = (const float*)d_in[5];
    const float* a2 = (const float*)d_in[6];
    const float* wa = (const float*)d_in[7];
    const float* ba = (const float*)d_in[8];
    const float* aa = (const float*)d_in[9];
    float* out = (float*)d_out;

    cudaFuncSetAttribute(flash_kernel, cudaFuncAttributeMaxDynamicSharedMemorySize, SMEM_BYTES);

    stage1_kernel<<<dim3(HW / 64, 512 / 64, NB), 256>>>(x, w1, b1, a1, w2, b2, a2, wa, ba, aa);
    flash_kernel<<<dim3(HW / BQ, NB), 256, SMEM_BYTES>>>(x, out);
}

// round 3
// speedup vs baseline: 1.7076x; 1.7076x over previous
#include <cuda_runtime.h>
#include <math.h>
#include <stdint.h>

#define HW  4096
#define CH  256
#define NB  4

// Scratch: [N][512][HW]  rows 0..127 = q, 128..255 = k, 256..511 = v
__device__ float g_qkv[(size_t)NB * 512 * HW];

// ---------------------------------------------------------------------------
__device__ __forceinline__ float to_tf32(float x) {
    uint32_t r;
    asm("cvt.rna.tf32.f32 %0, %1;" : "=r"(r) : "f"(x));
    return __uint_as_float(r);
}

__device__ __forceinline__ void mma8(float* d, const float* a, const float* b) {
    asm volatile(
        "mma.sync.aligned.m16n8k8.row.col.f32.tf32.tf32.f32 "
        "{%0,%1,%2,%3},{%4,%5,%6,%7},{%8,%9},{%0,%1,%2,%3};\n"
        : "+f"(d[0]), "+f"(d[1]), "+f"(d[2]), "+f"(d[3])
        : "r"(__float_as_uint(a[0])), "r"(__float_as_uint(a[1])),
          "r"(__float_as_uint(a[2])), "r"(__float_as_uint(a[3])),
          "r"(__float_as_uint(b[0])), "r"(__float_as_uint(b[1])));
}

// Fast e^x on the FMA pipe (2^y split, Taylor-5 for 2^f, |rel err| ~3e-6)
__device__ __forceinline__ float fexp(float x) {
    float y = fmaxf(x * 1.4426950408889634f, -126.0f);
    float n = rintf(y);
    float f = y - n;
    float p = 1.3333558e-3f;
    p = p * f + 9.6181291e-3f;
    p = p * f + 5.5504109e-2f;
    p = p * f + 2.4022650e-1f;
    p = p * f + 6.9314718e-1f;
    p = p * f + 1.0f;
    return p * __int_as_float(((int)n + 127) << 23);
}

// ---------------------------------------------------------------------------
// Stage 1: out[o][hw] = PReLU(sum_c W[o][c] * x[c][hw] + b[o]) via tf32 mma
// ---------------------------------------------------------------------------
#define S1_AST 260            /* A stride: %32==4 -> conflict-free A-frag */
#define S1_BST 72             /* B stride: %32==8 -> conflict-free B-frag */
#define S1_SMEM ((64*S1_AST + 64*S1_BST) * 4)

__global__ void __launch_bounds__(256) stage1_kernel(
    const float* __restrict__ x,
    const float* __restrict__ w1, const float* __restrict__ b1, const float* __restrict__ a1,
    const float* __restrict__ w2, const float* __restrict__ b2, const float* __restrict__ a2,
    const float* __restrict__ wa, const float* __restrict__ ba, const float* __restrict__ aa)
{
    extern __shared__ float sm[];
    float* As = sm;                 // [64][260]  W tile (o-major, natural)
    float* Bs = sm + 64 * S1_AST;   // [64][72]   x chunk (c-major, natural)

    const int hbase = blockIdx.x * 64;
    const int obase = blockIdx.y * 64;
    const int n     = blockIdx.z;
    const int tid   = threadIdx.x;
    const int w = tid >> 5, lane = tid & 31, grp = lane >> 2, qd = lane & 3;

    const float* xb = x + (size_t)n * CH * HW;

    // Load full W tile [64][256] once
    for (int idx = tid; idx < 64 * 256; idx += 256) {
        int oo = idx >> 8, c = idx & 255;
        int o = obase + oo;
        const float* wp = (o < 128) ? w1 + (size_t)o * CH
                        : (o < 256) ? w2 + (size_t)(o - 128) * CH
                                    : wa + (size_t)(o - 256) * CH;
        As[oo * S1_AST + c] = to_tf32(wp[c]);
    }

    const int ot  = w & 3;          // o row tile (16 rows)
    const int hb0 = (w >> 2) * 4;   // 4 hw col tiles (n=8 each)
    float acc[4][4] = {};

    for (int cc = 0; cc < 4; ++cc) {           // 64-channel chunks
        __syncthreads();
        for (int idx = tid; idx < 64 * 64; idx += 256) {
            int cl = idx >> 6, hh = idx & 63;
            Bs[cl * S1_BST + hh] = to_tf32(xb[(size_t)(cc * 64 + cl) * HW + hbase + hh]);
        }
        __syncthreads();
        #pragma unroll
        for (int cs = 0; cs < 8; ++cs) {
            float a[4];
            int ab = (ot * 16 + grp) * S1_AST + cc * 64 + cs * 8 + qd;
            a[0] = As[ab];               a[1] = As[ab + 8 * S1_AST];
            a[2] = As[ab + 4];           a[3] = As[ab + 8 * S1_AST + 4];
            #pragma unroll
            for (int t = 0; t < 4; ++t) {
                float b[2];
                int bb = (cs * 8 + qd) * S1_BST + (hb0 + t) * 8 + grp;
                b[0] = Bs[bb];
                b[1] = Bs[bb + 4 * S1_BST];
                mma8(acc[t], a, b);
            }
        }
    }

    // Epilogue: bias + PReLU -> g_qkv
    const int o0 = obase + ot * 16 + grp;
    const int o1 = o0 + 8;
    float bias0, slope0, bias1, slope1;
    {
        if (o0 < 128)      { bias0 = b1[o0];       slope0 = a1[0]; }
        else if (o0 < 256) { bias0 = b2[o0 - 128]; slope0 = a2[0]; }
        else               { bias0 = ba[o0 - 256]; slope0 = aa[0]; }
        if (o1 < 128)      { bias1 = b1[o1];       slope1 = a1[0]; }
        else if (o1 < 256) { bias1 = b2[o1 - 128]; slope1 = a2[0]; }
        else               { bias1 = ba[o1 - 256]; slope1 = aa[0]; }
    }
    float* gout = g_qkv + (size_t)n * 512 * HW;
    #pragma unroll
    for (int t = 0; t < 4; ++t) {
        int hw0 = hbase + (hb0 + t) * 8 + 2 * qd;
        float v00 = acc[t][0] + bias0; v00 = v00 >= 0.f ? v00 : slope0 * v00;
        float v01 = acc[t][1] + bias0; v01 = v01 >= 0.f ? v01 : slope0 * v01;
        float v10 = acc[t][2] + bias1; v10 = v10 >= 0.f ? v10 : slope1 * v10;
        float v11 = acc[t][3] + bias1; v11 = v11 >= 0.f ? v11 : slope1 * v11;
        *(float2*)(gout + (size_t)o0 * HW + hw0) = make_float2(v00, v01);
        *(float2*)(gout + (size_t)o1 * HW + hw0) = make_float2(v10, v11);
    }
}

// ---------------------------------------------------------------------------
// Flash attention, tf32 mma. S = Q^T K (c=128), O^T[cc][q] = V · P^T (k=64/step)
// ---------------------------------------------------------------------------
#define QT_ST 132   /* Qt [64 q][132]  (%32==4, A-frag conflict-free)      */
#define KS_ST 72    /* Ks [128 c][72]  natural (%32==8, B-frag conflict-free)*/
#define VS_ST 68    /* Vs [256 c][68]  natural (%32==4, A-frag conflict-free)*/
#define PS_ST 68    /* Ps [64 q][68]                                         */
#define OFF_QT 0
#define OFF_KS (64 * QT_ST)
#define OFF_VS (OFF_KS + 128 * KS_ST)
#define OFF_PS (OFF_VS + 256 * VS_ST)
#define OFF_M  (OFF_PS + 64 * PS_ST)
#define OFF_L  (OFF_M + 64)
#define OFF_CF (OFF_L + 64)
#define FL_SMEM ((OFF_CF + 64) * 4)

__global__ void __launch_bounds__(256) flash_kernel(
    const float* __restrict__ x, float* __restrict__ out)
{
    extern __shared__ float sm[];
    float* Qt   = sm + OFF_QT;
    float* Ks   = sm + OFF_KS;
    float* Vs   = sm + OFF_VS;
    float* Ps   = sm + OFF_PS;
    float* mrow = sm + OFF_M;
    float* lrow = sm + OFF_L;
    float* crow = sm + OFF_CF;

    const int qtile = blockIdx.x, n = blockIdx.y;
    const int qbase = qtile * 64;
    const int tid = threadIdx.x;
    const int w = tid >> 5, lane = tid & 31, grp = lane >> 2, qd = lane & 3;

    const float* Q = g_qkv + (size_t)n * 512 * HW;
    const float* K = Q + (size_t)128 * HW;
    const float* V = Q + (size_t)256 * HW;

    // Q tile -> transposed [q][c] (once per CTA)
    for (int idx = tid; idx < 128 * 64; idx += 256) {
        int c = idx >> 6, i = idx & 63;
        Qt[i * QT_ST + c] = to_tf32(Q[(size_t)c * HW + qbase + i]);
    }
    if (tid < 64) { mrow[tid] = -1e30f; lrow[tid] = 0.f; }

    const int s_qt  = w & 3;          // QK: q row tile
    const int s_kb0 = (w >> 2) * 4;   // QK: 4 key col tiles
    const int o_ct0 = (w & 3) * 4;    // PV: 4 cc row tiles (16 rows each)
    const int o_qn0 = (w >> 2) * 4;   // PV: 4 q col tiles (8 cols each)

    float acc[4][4][4] = {};          // O^T fragments [cc-tile][q-tile][4]

    const int srow = tid >> 2;        // softmax: 4 threads per row
    const int sseg = tid & 3;

    for (int kt = 0; kt < HW / 64; ++kt) {
        const int kbase = kt * 64;
        __syncthreads();
        // Load K [128][64], V [256][64] in natural layout (conflict-free)
        for (int idx = tid; idx < 128 * 64; idx += 256) {
            int c = idx >> 6, j = idx & 63;
            Ks[c * KS_ST + j] = to_tf32(K[(size_t)c * HW + kbase + j]);
        }
        for (int idx = tid; idx < 256 * 64; idx += 256) {
            int c = idx >> 6, j = idx & 63;
            Vs[c * VS_ST + j] = to_tf32(V[(size_t)c * HW + kbase + j]);
        }
        __syncthreads();

        // ---- S = Q^T K ----
        float s[4][4] = {};
        #pragma unroll
        for (int cs = 0; cs < 16; ++cs) {
            float a[4];
            int ab = (s_qt * 16 + grp) * QT_ST + cs * 8 + qd;
            a[0] = Qt[ab];     a[1] = Qt[ab + 8 * QT_ST];
            a[2] = Qt[ab + 4]; a[3] = Qt[ab + 8 * QT_ST + 4];
            #pragma unroll
            for (int t = 0; t < 4; ++t) {
                float b[2];
                int bb = (cs * 8 + qd) * KS_ST + (s_kb0 + t) * 8 + grp;
                b[0] = Ks[bb];
                b[1] = Ks[bb + 4 * KS_ST];
                mma8(s[t], a, b);
            }
        }
        #pragma unroll
        for (int t = 0; t < 4; ++t) {
            int pb = (s_qt * 16 + grp) * PS_ST + (s_kb0 + t) * 8 + 2 * qd;
            *(float2*)(Ps + pb)              = make_float2(s[t][0], s[t][1]);
            *(float2*)(Ps + pb + 8 * PS_ST)  = make_float2(s[t][2], s[t][3]);
        }
        __syncthreads();

        // ---- online softmax (4 threads / row, FMA-pipe exp) ----
        {
            float v[16];
            float* pr = Ps + srow * PS_ST + sseg * 16;
            float mx = -1e30f;
            #pragma unroll
            for (int j = 0; j < 16; ++j) { v[j] = pr[j]; mx = fmaxf(mx, v[j]); }
            mx = fmaxf(mx, __shfl_xor_sync(0xffffffffu, mx, 1));
            mx = fmaxf(mx, __shfl_xor_sync(0xffffffffu, mx, 2));
            float mo = mrow[srow];
            float mn = fmaxf(mo, mx);
            float sum = 0.f;
            #pragma unroll
            for (int j = 0; j < 16; ++j) {
                float p = fexp(v[j] - mn);
                sum += p;
                pr[j] = to_tf32(p);
            }
            sum += __shfl_xor_sync(0xffffffffu, sum, 1);
            sum += __shfl_xor_sync(0xffffffffu, sum, 2);
            if (sseg == 0) {
                float cf = fexp(mo - mn);
                mrow[srow] = mn;
                lrow[srow] = lrow[srow] * cf + sum;
                crow[srow] = cf;
            }
        }
        __syncthreads();

        // ---- rescale + O^T += V P^T ----
        #pragma unroll
        for (int j = 0; j < 4; ++j) {
            float cfa = crow[(o_qn0 + j) * 8 + 2 * qd];
            float cfb = crow[(o_qn0 + j) * 8 + 2 * qd + 1];
            #pragma unroll
            for (int i = 0; i < 4; ++i) {
                acc[i][j][0] *= cfa; acc[i][j][1] *= cfb;
                acc[i][j][2] *= cfa; acc[i][j][3] *= cfb;
            }
        }
        #pragma unroll
        for (int ks = 0; ks < 8; ++ks) {
            float a[4][4];
            #pragma unroll
            for (int i = 0; i < 4; ++i) {
                int ab = ((o_ct0 + i) * 16 + grp) * VS_ST + ks * 8 + qd;
                a[i][0] = Vs[ab];     a[i][1] = Vs[ab + 8 * VS_ST];
                a[i][2] = Vs[ab + 4]; a[i][3] = Vs[ab + 8 * VS_ST + 4];
            }
            #pragma unroll
            for (int j = 0; j < 4; ++j) {
                float b[2];
                int bb = ((o_qn0 + j) * 8 + grp) * PS_ST + ks * 8 + qd;
                b[0] = Ps[bb];
                b[1] = Ps[bb + 4];
                #pragma unroll
                for (int i = 0; i < 4; ++i) mma8(acc[i][j], a[i], b);
            }
        }
    }

    // ---- epilogue: /l + residual, O^T is already [c][hw] ----
    __syncthreads();
    const float* xb = x + (size_t)n * CH * HW;
    float* ob = out + (size_t)n * CH * HW;
    #pragma unroll
    for (int j = 0; j < 4; ++j) {
        int q0 = (o_qn0 + j) * 8 + 2 * qd;
        float inv0 = 1.f / lrow[q0];
        float inv1 = 1.f / lrow[q0 + 1];
        #pragma unroll
        for (int i = 0; i < 4; ++i) {
            int cc0 = (o_ct0 + i) * 16 + grp;
            size_t g0 = (size_t)cc0 * HW + qbase + q0;
            size_t g1 = (size_t)(cc0 + 8) * HW + qbase + q0;
            float2 x0 = *(const float2*)(xb + g0);
            float2 x1 = *(const float2*)(xb + g1);
            *(float2*)(ob + g0) = make_float2(acc[i][j][0] * inv0 + x0.x,
                                              acc[i][j][1] * inv1 + x0.y);
            *(float2*)(ob + g1) = make_float2(acc[i][j][2] * inv0 + x1.x,
                                              acc[i][j][3] * inv1 + x1.y);
        }
    }
}

// ---------------------------------------------------------------------------
extern "C" void kernel_launch(void* const* d_in, const int* in_sizes, int n_in,
                              void* d_out, int out_size)
{
    const float* x  = (const float*)d_in[0];
    const float* w1 = (const float*)d_in[1];
    const float* b1 = (const float*)d_in[2];
    const float* a1 = (const float*)d_in[3];
    const float* w2 = (const float*)d_in[4];
    const float* b2 = (const float*)d_in[5];
    const float* a2 = (const float*)d_in[6];
    const float* wa = (const float*)d_in[7];
    const float* ba = (const float*)d_in[8];
    const float* aa = (const float*)d_in[9];
    float* out = (float*)d_out;

    cudaFuncSetAttribute(stage1_kernel, cudaFuncAttributeMaxDynamicSharedMemorySize, S1_SMEM);
    cudaFuncSetAttribute(flash_kernel,  cudaFuncAttributeMaxDynamicSharedMemorySize, FL_SMEM);

    stage1_kernel<<<dim3(HW / 64, 8, NB), 256, S1_SMEM>>>(x, w1, b1, a1, w2, b2, a2, wa, ba, aa);
    flash_kernel<<<dim3(HW / 64, NB), 256, FL_SMEM>>>(x, out);
}

// round 4
// speedup vs baseline: 3.6019x; 2.1093x over previous
#include <cuda_runtime.h>
#include <math.h>
#include <stdint.h>

#define HW  4096
#define CH  256
#define NB  4

// Scratch: [N][512][HW]  rows 0..127 = q, 128..255 = k, 256..511 = v
__device__ float g_qkv[(size_t)NB * 512 * HW];

// ---------------------------------------------------------------------------
__device__ __forceinline__ float to_tf32(float x) {
    uint32_t r;
    asm("cvt.rna.tf32.f32 %0, %1;" : "=r"(r) : "f"(x));
    return __uint_as_float(r);
}

__device__ __forceinline__ void mma8(float* d, const float* a, const float* b) {
    asm volatile(
        "mma.sync.aligned.m16n8k8.row.col.f32.tf32.tf32.f32 "
        "{%0,%1,%2,%3},{%4,%5,%6,%7},{%8,%9},{%0,%1,%2,%3};\n"
        : "+f"(d[0]), "+f"(d[1]), "+f"(d[2]), "+f"(d[3])
        : "r"(__float_as_uint(a[0])), "r"(__float_as_uint(a[1])),
          "r"(__float_as_uint(a[2])), "r"(__float_as_uint(a[3])),
          "r"(__float_as_uint(b[0])), "r"(__float_as_uint(b[1])));
}

__device__ __forceinline__ void mma_u(float* d, const uint32_t* a, uint32_t b0, uint32_t b1) {
    asm volatile(
        "mma.sync.aligned.m16n8k8.row.col.f32.tf32.tf32.f32 "
        "{%0,%1,%2,%3},{%4,%5,%6,%7},{%8,%9},{%0,%1,%2,%3};\n"
        : "+f"(d[0]), "+f"(d[1]), "+f"(d[2]), "+f"(d[3])
        : "r"(a[0]), "r"(a[1]), "r"(a[2]), "r"(a[3]), "r"(b0), "r"(b1));
}

__device__ __forceinline__ void ldsm_x4(uint32_t* r, uint32_t saddr) {
    asm volatile("ldmatrix.sync.aligned.m8n8.x4.shared.b16 {%0,%1,%2,%3}, [%4];"
                 : "=r"(r[0]), "=r"(r[1]), "=r"(r[2]), "=r"(r[3]) : "r"(saddr));
}

__device__ __forceinline__ void cp_async16(uint32_t saddr, const void* gptr) {
    asm volatile("cp.async.ca.shared.global [%0], [%1], 16;\n" :: "r"(saddr), "l"(gptr));
}
__device__ __forceinline__ void cp_async_wait_all() {
    asm volatile("cp.async.commit_group;\ncp.async.wait_group 0;\n" ::: "memory");
}

// Fast e^x on the FMA pipe (2^y split, Taylor-5 for 2^f, |rel err| ~3e-6)
__device__ __forceinline__ float fexp(float x) {
    float y = fmaxf(x * 1.4426950408889634f, -126.0f);
    float n = rintf(y);
    float f = y - n;
    float p = 1.3333558e-3f;
    p = p * f + 9.6181291e-3f;
    p = p * f + 5.5504109e-2f;
    p = p * f + 2.4022650e-1f;
    p = p * f + 6.9314718e-1f;
    p = p * f + 1.0f;
    return p * __int_as_float(((int)n + 127) << 23);
}

// ---------------------------------------------------------------------------
// Stage 1 (unchanged from round 3): stacked 1x1 conv GEMM via tf32 mma
// ---------------------------------------------------------------------------
#define S1_AST 260
#define S1_BST 72
#define S1_SMEM ((64*S1_AST + 64*S1_BST) * 4)

__global__ void __launch_bounds__(256) stage1_kernel(
    const float* __restrict__ x,
    const float* __restrict__ w1, const float* __restrict__ b1, const float* __restrict__ a1,
    const float* __restrict__ w2, const float* __restrict__ b2, const float* __restrict__ a2,
    const float* __restrict__ wa, const float* __restrict__ ba, const float* __restrict__ aa)
{
    extern __shared__ float sm[];
    float* As = sm;
    float* Bs = sm + 64 * S1_AST;

    const int hbase = blockIdx.x * 64;
    const int obase = blockIdx.y * 64;
    const int n     = blockIdx.z;
    const int tid   = threadIdx.x;
    const int w = tid >> 5, lane = tid & 31, grp = lane >> 2, qd = lane & 3;

    const float* xb = x + (size_t)n * CH * HW;

    for (int idx = tid; idx < 64 * 256; idx += 256) {
        int oo = idx >> 8, c = idx & 255;
        int o = obase + oo;
        const float* wp = (o < 128) ? w1 + (size_t)o * CH
                        : (o < 256) ? w2 + (size_t)(o - 128) * CH
                                    : wa + (size_t)(o - 256) * CH;
        As[oo * S1_AST + c] = to_tf32(wp[c]);
    }

    const int ot  = w & 3;
    const int hb0 = (w >> 2) * 4;
    float acc[4][4] = {};

    for (int cc = 0; cc < 4; ++cc) {
        __syncthreads();
        for (int idx = tid; idx < 64 * 64; idx += 256) {
            int cl = idx >> 6, hh = idx & 63;
            Bs[cl * S1_BST + hh] = to_tf32(xb[(size_t)(cc * 64 + cl) * HW + hbase + hh]);
        }
        __syncthreads();
        #pragma unroll
        for (int cs = 0; cs < 8; ++cs) {
            float a[4];
            int ab = (ot * 16 + grp) * S1_AST + cc * 64 + cs * 8 + qd;
            a[0] = As[ab];               a[1] = As[ab + 8 * S1_AST];
            a[2] = As[ab + 4];           a[3] = As[ab + 8 * S1_AST + 4];
            #pragma unroll
            for (int t = 0; t < 4; ++t) {
                float b[2];
                int bb = (cs * 8 + qd) * S1_BST + (hb0 + t) * 8 + grp;
                b[0] = Bs[bb];
                b[1] = Bs[bb + 4 * S1_BST];
                mma8(acc[t], a, b);
            }
        }
    }

    const int o0 = obase + ot * 16 + grp;
    const int o1 = o0 + 8;
    float bias0, slope0, bias1, slope1;
    {
        if (o0 < 128)      { bias0 = b1[o0];       slope0 = a1[0]; }
        else if (o0 < 256) { bias0 = b2[o0 - 128]; slope0 = a2[0]; }
        else               { bias0 = ba[o0 - 256]; slope0 = aa[0]; }
        if (o1 < 128)      { bias1 = b1[o1];       slope1 = a1[0]; }
        else if (o1 < 256) { bias1 = b2[o1 - 128]; slope1 = a2[0]; }
        else               { bias1 = ba[o1 - 256]; slope1 = aa[0]; }
    }
    float* gout = g_qkv + (size_t)n * 512 * HW;
    #pragma unroll
    for (int t = 0; t < 4; ++t) {
        int hw0 = hbase + (hb0 + t) * 8 + 2 * qd;
        float v00 = acc[t][0] + bias0; v00 = v00 >= 0.f ? v00 : slope0 * v00;
        float v01 = acc[t][1] + bias0; v01 = v01 >= 0.f ? v01 : slope0 * v01;
        float v10 = acc[t][2] + bias1; v10 = v10 >= 0.f ? v10 : slope1 * v10;
        float v11 = acc[t][3] + bias1; v11 = v11 >= 0.f ? v11 : slope1 * v11;
        *(float2*)(gout + (size_t)o0 * HW + hw0) = make_float2(v00, v01);
        *(float2*)(gout + (size_t)o1 * HW + hw0) = make_float2(v10, v11);
    }
}

// ---------------------------------------------------------------------------
// Flash attention: BQ=128, BK=64, 512 threads, ldmatrix tf32 fragments.
//   Qt  [128 q][132 c]   (A-op for QK)
//   KsT [64 j][132 c]    (B-op for QK; K transposed on load)
//   Vs  [256 c][68 j]    (A-op for PV; cp.async, raw f32)
//   Ps  [128 q][68 k]    (C written by QK, rows read by softmax, B-op for PV)
// ---------------------------------------------------------------------------
#define QT_ST 132
#define KT_ST 132
#define VS_ST 68
#define PS_ST 68
#define OFF_QT 0
#define OFF_KT (128 * QT_ST)                 /* 16896 */
#define OFF_VS (OFF_KT + 64 * KT_ST)         /* 25344 */
#define OFF_PS (OFF_VS + 256 * VS_ST)        /* 42752 */
#define OFF_M  (OFF_PS + 128 * PS_ST)        /* 51456 */
#define OFF_L  (OFF_M + 128)
#define OFF_CF (OFF_L + 128)
#define FL_FLOATS (OFF_CF + 128)             /* 51840 */
#define FL_SMEM (FL_FLOATS * 4)              /* 207360 B */

__global__ void __launch_bounds__(512, 1) flash_kernel(
    const float* __restrict__ x, float* __restrict__ out)
{
    extern __shared__ float sm[];
    float* Qt   = sm + OFF_QT;
    float* KsT  = sm + OFF_KT;
    float* Ps   = sm + OFF_PS;
    float* mrow = sm + OFF_M;
    float* lrow = sm + OFF_L;
    float* crow = sm + OFF_CF;

    const uint32_t sbase = (uint32_t)__cvta_generic_to_shared(sm);

    const int qtile = blockIdx.x, n = blockIdx.y;
    const int qbase = qtile * 128;
    const int tid  = threadIdx.x;
    const int w    = tid >> 5, lane = tid & 31;
    const int grp  = lane >> 2, qd = lane & 3;

    const float* Q = g_qkv + (size_t)n * 512 * HW;
    const float* K = Q + (size_t)128 * HW;
    const float* V = Q + (size_t)256 * HW;

    // ldmatrix per-thread address parts
    const int rpA = (lane & 7) + (lane & 8);       // A-frag row part
    const int cpA = ((lane >> 4) & 1) * 4;         // A-frag col part
    const int rpB = lane & 7;                      // B-frag row part
    const int cpB = (lane >> 3) * 4;               // B-frag col part

    // Warp tiling
    const int mq0 = (w & 3) * 32;       // QK: 2 m16 q-tiles
    const int nk0 = (w >> 2) * 16;      // QK: 2 n8 k-tiles
    const int vm0 = (w & 3) * 64;       // PV: 4 m16 c-tiles
    const int qn0 = (w >> 2) * 32;      // PV: 4 n8 q-tiles

    const uint32_t qa_base = sbase + (uint32_t)(OFF_QT + (mq0 + rpA) * QT_ST + cpA) * 4u;
    const uint32_t kb_base = sbase + (uint32_t)(OFF_KT + (nk0 + rpB) * KT_ST + cpB) * 4u;
    const uint32_t va_base = sbase + (uint32_t)(OFF_VS + (vm0 + rpA) * VS_ST + cpA) * 4u;
    const uint32_t pb_base = sbase + (uint32_t)(OFF_PS + (qn0 + rpB) * PS_ST + cpB) * 4u;

    // Load Q tile transposed [q][c] (once)
    for (int idx = tid; idx < 128 * 128; idx += 512) {
        int c = idx >> 7, i = idx & 127;
        Qt[i * QT_ST + c] = to_tf32(Q[(size_t)c * HW + qbase + i]);
    }
    if (tid < 128) { mrow[tid] = -1e30f; lrow[tid] = 0.f; }

    float acc[4][4][4] = {};     // O^T fragments [c-tile][q-tile][4]

    const int srow = tid >> 2;   // softmax: 4 threads per row, 16 cols each
    const int sseg = tid & 3;

    for (int kt = 0; kt < HW / 64; ++kt) {
        const int kbase = kt * 64;
        __syncthreads();
        // V tile via cp.async (raw f32; mma tf32 truncates mantissa)
        {
            const uint32_t vdst = sbase + (uint32_t)OFF_VS * 4u;
            for (int idx = tid; idx < 4096; idx += 512) {
                int c = idx >> 4, ch = idx & 15;
                cp_async16(vdst + (uint32_t)(c * VS_ST + ch * 4) * 4u,
                           V + (size_t)c * HW + kbase + ch * 4);
            }
        }
        // K tile transposed [j][c]
        for (int idx = tid; idx < 128 * 64; idx += 512) {
            int c = idx >> 6, j = idx & 63;
            KsT[j * KT_ST + c] = to_tf32(K[(size_t)c * HW + kbase + j]);
        }
        cp_async_wait_all();
        __syncthreads();

        // ---- S = Q^T K : [128 q][64 k], per warp 2x2 m16n8 tiles ----
        {
            float s[2][2][4] = {};
            #pragma unroll
            for (int sp = 0; sp < 8; ++sp) {          // k16 steps over c=128
                uint32_t bq[2][4];
                #pragma unroll
                for (int ni = 0; ni < 2; ++ni)
                    ldsm_x4(bq[ni], kb_base + (uint32_t)(ni * 8 * KT_ST + sp * 16) * 4u);
                #pragma unroll
                for (int sub = 0; sub < 2; ++sub) {
                    uint32_t av[2][4];
                    #pragma unroll
                    for (int mi = 0; mi < 2; ++mi)
                        ldsm_x4(av[mi], qa_base + (uint32_t)(mi * 16 * QT_ST + (sp * 2 + sub) * 8) * 4u);
                    #pragma unroll
                    for (int mi = 0; mi < 2; ++mi)
                        #pragma unroll
                        for (int ni = 0; ni < 2; ++ni)
                            mma_u(s[mi][ni], av[mi], bq[ni][2 * sub], bq[ni][2 * sub + 1]);
                }
            }
            #pragma unroll
            for (int mi = 0; mi < 2; ++mi)
                #pragma unroll
                for (int ni = 0; ni < 2; ++ni) {
                    int row = mq0 + mi * 16 + grp;
                    int col = nk0 + ni * 8 + 2 * qd;
                    *(float2*)(Ps + row * PS_ST + col)       = make_float2(s[mi][ni][0], s[mi][ni][1]);
                    *(float2*)(Ps + (row + 8) * PS_ST + col) = make_float2(s[mi][ni][2], s[mi][ni][3]);
                }
        }
        __syncthreads();

        // ---- online softmax (4 threads / row) ----
        {
            float* pr = Ps + srow * PS_ST + sseg * 16;
            float v[16];
            float mx = -1e30f;
            #pragma unroll
            for (int j4 = 0; j4 < 4; ++j4) {
                float4 t = *(const float4*)(pr + 4 * j4);
                v[4*j4+0] = t.x; v[4*j4+1] = t.y; v[4*j4+2] = t.z; v[4*j4+3] = t.w;
            }
            #pragma unroll
            for (int j = 0; j < 16; ++j) mx = fmaxf(mx, v[j]);
            mx = fmaxf(mx, __shfl_xor_sync(0xffffffffu, mx, 1));
            mx = fmaxf(mx, __shfl_xor_sync(0xffffffffu, mx, 2));
            float mo = mrow[srow];
            float mn = fmaxf(mo, mx);
            float sum = 0.f;
            #pragma unroll
            for (int j4 = 0; j4 < 4; ++j4) {
                float4 t;
                float p0 = fexp(v[4*j4+0] - mn);
                float p1 = fexp(v[4*j4+1] - mn);
                float p2 = fexp(v[4*j4+2] - mn);
                float p3 = fexp(v[4*j4+3] - mn);
                sum += (p0 + p1) + (p2 + p3);
                t.x = to_tf32(p0); t.y = to_tf32(p1); t.z = to_tf32(p2); t.w = to_tf32(p3);
                *(float4*)(pr + 4 * j4) = t;
            }
            sum += __shfl_xor_sync(0xffffffffu, sum, 1);
            sum += __shfl_xor_sync(0xffffffffu, sum, 2);
            if (sseg == 0) {
                float cf = fexp(mo - mn);
                mrow[srow] = mn;
                lrow[srow] = lrow[srow] * cf + sum;
                crow[srow] = cf;
            }
        }
        __syncthreads();

        // ---- rescale + O^T += V P^T : per warp 4x4 m16n8 tiles ----
        #pragma unroll
        for (int ni = 0; ni < 4; ++ni) {
            int q0 = qn0 + ni * 8 + 2 * qd;
            float cf0 = crow[q0], cf1 = crow[q0 + 1];
            #pragma unroll
            for (int mi = 0; mi < 4; ++mi) {
                acc[mi][ni][0] *= cf0; acc[mi][ni][1] *= cf1;
                acc[mi][ni][2] *= cf0; acc[mi][ni][3] *= cf1;
            }
        }
        #pragma unroll
        for (int sp = 0; sp < 4; ++sp) {              // k16 steps over k=64
            uint32_t bq[4][4];
            #pragma unroll
            for (int ni = 0; ni < 4; ++ni)
                ldsm_x4(bq[ni], pb_base + (uint32_t)(ni * 8 * PS_ST + sp * 16) * 4u);
            #pragma unroll
            for (int sub = 0; sub < 2; ++sub) {
                uint32_t av[4][4];
                #pragma unroll
                for (int mi = 0; mi < 4; ++mi)
                    ldsm_x4(av[mi], va_base + (uint32_t)(mi * 16 * VS_ST + (sp * 2 + sub) * 8) * 4u);
                #pragma unroll
                for (int mi = 0; mi < 4; ++mi)
                    #pragma unroll
                    for (int ni = 0; ni < 4; ++ni)
                        mma_u(acc[mi][ni], av[mi], bq[ni][2 * sub], bq[ni][2 * sub + 1]);
            }
        }
    }

    // ---- epilogue: /l + residual; O^T already [c][hw] ----
    const float* xb = x + (size_t)n * CH * HW;
    float* ob = out + (size_t)n * CH * HW;
    #pragma unroll
    for (int ni = 0; ni < 4; ++ni) {
        int q0 = qn0 + ni * 8 + 2 * qd;
        float inv0 = 1.f / lrow[q0];
        float inv1 = 1.f / lrow[q0 + 1];
        #pragma unroll
        for (int mi = 0; mi < 4; ++mi) {
            int c0 = vm0 + mi * 16 + grp;
            size_t g0 = (size_t)c0 * HW + qbase + q0;
            size_t g1 = (size_t)(c0 + 8) * HW + qbase + q0;
            float2 x0 = *(const float2*)(xb + g0);
            float2 x1 = *(const float2*)(xb + g1);
            *(float2*)(ob + g0) = make_float2(acc[mi][ni][0] * inv0 + x0.x,
                                              acc[mi][ni][1] * inv1 + x0.y);
            *(float2*)(ob + g1) = make_float2(acc[mi][ni][2] * inv0 + x1.x,
                                              acc[mi][ni][3] * inv1 + x1.y);
        }
    }
}

// ---------------------------------------------------------------------------
extern "C" void kernel_launch(void* const* d_in, const int* in_sizes, int n_in,
                              void* d_out, int out_size)
{
    const float* x  = (const float*)d_in[0];
    const float* w1 = (const float*)d_in[1];
    const float* b1 = (const float*)d_in[2];
    const float* a1 = (const float*)d_in[3];
    const float* w2 = (const float*)d_in[4];
    const float* b2 = (const float*)d_in[5];
    const float* a2 = (const float*)d_in[6];
    const float* wa = (const float*)d_in[7];
    const float* ba = (const float*)d_in[8];
    const float* aa = (const float*)d_in[9];
    float* out = (float*)d_out;

    cudaFuncSetAttribute(stage1_kernel, cudaFuncAttributeMaxDynamicSharedMemorySize, S1_SMEM);
    cudaFuncSetAttribute(flash_kernel,  cudaFuncAttributeMaxDynamicSharedMemorySize, FL_SMEM);

    stage1_kernel<<<dim3(HW / 64, 8, NB), 256, S1_SMEM>>>(x, w1, b1, a1, w2, b2, a2, wa, ba, aa);
    flash_kernel<<<dim3(HW / 128, NB), 512, FL_SMEM>>>(x, out);
}